// round 1
// baseline (speedup 1.0000x reference)
#include <cuda_runtime.h>
#include <math.h>

#define Bq 4
#define Sq 2048
#define Eq 1024
#define Hq 8
#define Dq 128
#define BS (Bq*Sq)          /* 8192 tokens */
#define HD (Hq*Dq)          /* 1024 */

// ---------------- scratch (static device globals; no allocation) ----------------
__device__ float g_buf0[BS*HD];   // z (from GEMM-A) -> reused for h1 (GEMM-B out, scaled by scores)
__device__ float g_buf1[BS*HD];   // scan states -> hln (in-place per-head LN)
__device__ float g_buf2[BS*Eq];   // pre-output (GEMM-C out, before final LN)
__device__ float g_v[HD];         // v[h,d] = sum_e W2[h,d,e] * w_att[e]
__device__ float g_c[Hq];         // c[h]   = sum_e b2[h,e]   * w_att[e]
__device__ float g_scores[BS*Hq]; // softmax scores per token/head

// ---------------- generic fp32 SIMT GEMM: 128x128 block, 8x8 per thread ----------------
// epi: 0 = tanh(acc + bias[col])            (GEMM-A)
//      1 = gelu_exact(acc + bias[col])      (GEMM-B, per-head via blockIdx.z)
//      2 = acc + sum_h scores[row,h]*b2[h,col]   (GEMM-C)
__global__ void __launch_bounds__(256, 2)
gemm_kernel(const float* __restrict__ A, int lda, int sAz,
            const float* __restrict__ B, int ldb, int sBz,
            float* __restrict__ C, int ldc, int sCz,
            int K,
            const float* __restrict__ bias, int sBiasz,
            int epi,
            const float* __restrict__ scores,
            const float* __restrict__ b2)
{
    __shared__ float As[16][128];
    __shared__ float Bs[16][128];

    const int tid = threadIdx.x;
    const int tx = tid & 15;        // 0..15 -> col groups of 8
    const int ty = tid >> 4;        // 0..15 -> row groups of 8
    const int bx = blockIdx.x, by = blockIdx.y, bz = blockIdx.z;

    A += bz * sAz + by * 128 * lda;
    B += bz * sBz + bx * 128;
    C += bz * sCz + by * 128 * ldc + bx * 128;
    const float* biasp = bias ? (bias + bz * sBiasz + bx * 128) : nullptr;

    const int a_row = tid >> 2;            // 0..63
    const int a_k   = (tid & 3) << 2;      // 0,4,8,12
    const int b_row = tid >> 5;            // 0..7
    const int b_n   = (tid & 31) << 2;     // 0..124

    float acc[8][8];
    #pragma unroll
    for (int i = 0; i < 8; i++)
        #pragma unroll
        for (int j = 0; j < 8; j++) acc[i][j] = 0.0f;

    for (int kt = 0; kt < K; kt += 16) {
        float4 av0 = *(const float4*)(A + a_row * lda + kt + a_k);
        float4 av1 = *(const float4*)(A + (a_row + 64) * lda + kt + a_k);
        float4 bv0 = *(const float4*)(B + (kt + b_row) * ldb + b_n);
        float4 bv1 = *(const float4*)(B + (kt + b_row + 8) * ldb + b_n);

        As[a_k + 0][a_row] = av0.x;  As[a_k + 1][a_row] = av0.y;
        As[a_k + 2][a_row] = av0.z;  As[a_k + 3][a_row] = av0.w;
        As[a_k + 0][a_row + 64] = av1.x;  As[a_k + 1][a_row + 64] = av1.y;
        As[a_k + 2][a_row + 64] = av1.z;  As[a_k + 3][a_row + 64] = av1.w;
        *(float4*)&Bs[b_row][b_n]     = bv0;
        *(float4*)&Bs[b_row + 8][b_n] = bv1;
        __syncthreads();

        #pragma unroll
        for (int k = 0; k < 16; k++) {
            float4 A0 = *(const float4*)&As[k][ty * 8];
            float4 A1 = *(const float4*)&As[k][ty * 8 + 4];
            float4 B0 = *(const float4*)&Bs[k][tx * 8];
            float4 B1 = *(const float4*)&Bs[k][tx * 8 + 4];
            float ar[8] = {A0.x, A0.y, A0.z, A0.w, A1.x, A1.y, A1.z, A1.w};
            float br[8] = {B0.x, B0.y, B0.z, B0.w, B1.x, B1.y, B1.z, B1.w};
            #pragma unroll
            for (int i = 0; i < 8; i++)
                #pragma unroll
                for (int j = 0; j < 8; j++)
                    acc[i][j] = fmaf(ar[i], br[j], acc[i][j]);
        }
        __syncthreads();
    }

    #pragma unroll
    for (int i = 0; i < 8; i++) {
        int grow = by * 128 + ty * 8 + i;
        float sc[8];
        if (epi == 2) {
            #pragma unroll
            for (int hh = 0; hh < 8; hh++) sc[hh] = scores[grow * 8 + hh];
        }
        #pragma unroll
        for (int j = 0; j < 8; j++) {
            float v = acc[i][j];
            int lcol = tx * 8 + j;
            if (epi == 0) {
                v = tanhf(v + biasp[lcol]);
            } else if (epi == 1) {
                float xx = v + biasp[lcol];
                v = 0.5f * xx * (1.0f + erff(xx * 0.70710678118654752f));
            } else {
                int gcol = bx * 128 + lcol;
                #pragma unroll
                for (int hh = 0; hh < 8; hh++)
                    v = fmaf(sc[hh], b2[hh * Eq + gcol], v);
            }
            C[(ty * 8 + i) * ldc + lcol] = v;
        }
    }
}

// ---------------- sequential MinimalRNN scan: one warp per (b,h) ----------------
__global__ void __launch_bounds__(32)
scan_kernel(const float* __restrict__ U_h, const float* __restrict__ U_z,
            const float* __restrict__ b_u,
            const float* __restrict__ lns_g, const float* __restrict__ lns_b)
{
    const int h = blockIdx.x;      // 0..7
    const int b = blockIdx.y;      // 0..3
    const int lane = threadIdx.x;
    const int d0 = lane * 4;

    float uh[4], uz[4], bu[4], gw[4], gb[4];
    #pragma unroll
    for (int c = 0; c < 4; c++) {
        int d = d0 + c;
        uh[c] = U_h[h * Dq * Dq + d * (Dq + 1)];   // diagonal
        uz[c] = U_z[h * Dq * Dq + d * (Dq + 1)];
        bu[c] = b_u[h * Dq + d];
        gw[c] = lns_g[d];
        gb[c] = lns_b[d];
    }

    float hp[4] = {0.f, 0.f, 0.f, 0.f};
    const int off = ((b * Sq) * Hq + h) * Dq + d0;
    float4 znext = *(const float4*)(g_buf0 + off);

    for (int t = 0; t < Sq; t++) {
        float zt[4] = {znext.x, znext.y, znext.z, znext.w};
        if (t + 1 < Sq)
            znext = *(const float4*)(g_buf0 + off + (t + 1) * HD);

        float hn[4];
        #pragma unroll
        for (int c = 0; c < 4; c++) {
            float a = fmaf(hp[c], uh[c], fmaf(zt[c], uz[c], bu[c]));
            float u = 1.0f / (1.0f + __expf(-a));
            hn[c] = fmaf(u, hp[c] - zt[c], zt[c]);   // u*hp + (1-u)*z
        }
        float s = (hn[0] + hn[1]) + (hn[2] + hn[3]);
        float q = fmaf(hn[0], hn[0], fmaf(hn[1], hn[1], fmaf(hn[2], hn[2], hn[3] * hn[3])));
        #pragma unroll
        for (int o = 16; o > 0; o >>= 1) {
            s += __shfl_xor_sync(0xffffffffu, s, o);
            q += __shfl_xor_sync(0xffffffffu, q, o);
        }
        float mean = s * (1.0f / Dq);
        float var  = q * (1.0f / Dq) - mean * mean;
        float r = rsqrtf(var + 1e-5f);
        #pragma unroll
        for (int c = 0; c < 4; c++)
            hp[c] = fmaf((hn[c] - mean) * r, gw[c], gb[c]);

        *(float4*)(g_buf1 + off + t * HD) = make_float4(hp[0], hp[1], hp[2], hp[3]);
    }
}

// ---------------- shaped = states*diag(out_shaper); per-head LN (in-place on g_buf1) ----------------
__global__ void __launch_bounds__(256)
hln_kernel(const float* __restrict__ out_shaper,
           const float* __restrict__ ffg, const float* __restrict__ ffb)
{
    int w    = blockIdx.x * 8 + (threadIdx.x >> 5);  // row 0..65535 = (b,s,h)
    int lane = threadIdx.x & 31;
    int h    = w & 7;
    int d0   = lane * 4;
    int off  = w * Dq + d0;

    float4 xv = *(const float4*)(g_buf1 + off);
    float xs[4] = {xv.x, xv.y, xv.z, xv.w};
    float sh[4];
    #pragma unroll
    for (int c = 0; c < 4; c++) {
        int d = d0 + c;
        sh[c] = xs[c] * out_shaper[h * Dq * Dq + d * (Dq + 1)];
    }
    float s = (sh[0] + sh[1]) + (sh[2] + sh[3]);
    float q = sh[0]*sh[0] + sh[1]*sh[1] + sh[2]*sh[2] + sh[3]*sh[3];
    #pragma unroll
    for (int o = 16; o > 0; o >>= 1) {
        s += __shfl_xor_sync(0xffffffffu, s, o);
        q += __shfl_xor_sync(0xffffffffu, q, o);
    }
    float mean = s * (1.0f / Dq);
    float var  = q * (1.0f / Dq) - mean * mean;
    float r = rsqrtf(var + 1e-5f);
    float4 ov;
    ov.x = fmaf((sh[0] - mean) * r, ffg[h * Dq + d0 + 0], ffb[h * Dq + d0 + 0]);
    ov.y = fmaf((sh[1] - mean) * r, ffg[h * Dq + d0 + 1], ffb[h * Dq + d0 + 1]);
    ov.z = fmaf((sh[2] - mean) * r, ffg[h * Dq + d0 + 2], ffb[h * Dq + d0 + 2]);
    ov.w = fmaf((sh[3] - mean) * r, ffg[h * Dq + d0 + 3], ffb[h * Dq + d0 + 3]);
    *(float4*)(g_buf1 + off) = ov;
}

// ---------------- precompute v[h,d] = W2[h,d,:]·w_att, c[h] = b2[h,:]·w_att ----------------
__global__ void __launch_bounds__(256)
prep_kernel(const float* __restrict__ W2, const float* __restrict__ b2,
            const float* __restrict__ watt)
{
    int w    = blockIdx.x * 8 + (threadIdx.x >> 5);
    int lane = threadIdx.x & 31;
    const float* rowp;
    if (w < HD)            rowp = W2 + w * Eq;
    else if (w < HD + Hq)  rowp = b2 + (w - HD) * Eq;
    else return;

    float p = 0.0f;
    for (int e = lane * 4; e < Eq; e += 128) {
        float4 a  = *(const float4*)(rowp + e);
        float4 ww = *(const float4*)(watt + e);
        p += a.x * ww.x + a.y * ww.y + a.z * ww.z + a.w * ww.w;
    }
    #pragma unroll
    for (int o = 16; o > 0; o >>= 1) p += __shfl_xor_sync(0xffffffffu, p, o);
    if (lane == 0) {
        if (w < HD) g_v[w] = p;
        else        g_c[w - HD] = p;
    }
}

// ---------------- per-token head softmax + scale h1 in place ----------------
__global__ void __launch_bounds__(256)
att_kernel()
{
    int token = blockIdx.x * 8 + (threadIdx.x >> 5);   // 0..8191
    int lane  = threadIdx.x & 31;
    int base  = token * HD;

    float4 xv[8];
    float lg[8];
    #pragma unroll
    for (int hh = 0; hh < 8; hh++) {
        xv[hh] = *(const float4*)(g_buf0 + base + hh * Dq + lane * 4);
        float4 vv = *(const float4*)(g_v + hh * Dq + lane * 4);
        float p = xv[hh].x * vv.x + xv[hh].y * vv.y + xv[hh].z * vv.z + xv[hh].w * vv.w;
        #pragma unroll
        for (int o = 16; o > 0; o >>= 1) p += __shfl_xor_sync(0xffffffffu, p, o);
        lg[hh] = p + g_c[hh];
    }
    float m = lg[0];
    #pragma unroll
    for (int hh = 1; hh < 8; hh++) m = fmaxf(m, lg[hh]);
    float ex[8]; float sum = 0.0f;
    #pragma unroll
    for (int hh = 0; hh < 8; hh++) { ex[hh] = __expf(lg[hh] - m); sum += ex[hh]; }
    float inv = 1.0f / sum;
    #pragma unroll
    for (int hh = 0; hh < 8; hh++) {
        float sc = ex[hh] * inv;
        xv[hh].x *= sc; xv[hh].y *= sc; xv[hh].z *= sc; xv[hh].w *= sc;
        *(float4*)(g_buf0 + base + hh * Dq + lane * 4) = xv[hh];
    }
    if (lane < 8) g_scores[token * 8 + lane] = ex[lane] * inv;
}

// ---------------- final LayerNorm over E -> d_out ----------------
__global__ void __launch_bounds__(256)
lnout_kernel(float* __restrict__ out, const float* __restrict__ g,
             const float* __restrict__ bb)
{
    int row  = blockIdx.x;
    int tid  = threadIdx.x;
    int base = row * Eq;

    float4 xv = *(const float4*)(g_buf2 + base + tid * 4);
    float s = xv.x + xv.y + xv.z + xv.w;
    float q = xv.x*xv.x + xv.y*xv.y + xv.z*xv.z + xv.w*xv.w;
    #pragma unroll
    for (int o = 16; o > 0; o >>= 1) {
        s += __shfl_xor_sync(0xffffffffu, s, o);
        q += __shfl_xor_sync(0xffffffffu, q, o);
    }
    __shared__ float rs[8], rq[8];
    __shared__ float mv[2];
    int warp = tid >> 5, lane = tid & 31;
    if (lane == 0) { rs[warp] = s; rq[warp] = q; }
    __syncthreads();
    if (tid == 0) {
        float S = 0.f, Q = 0.f;
        #pragma unroll
        for (int i = 0; i < 8; i++) { S += rs[i]; Q += rq[i]; }
        float mean = S * (1.0f / Eq);
        float var  = Q * (1.0f / Eq) - mean * mean;
        mv[0] = mean; mv[1] = rsqrtf(var + 1e-5f);
    }
    __syncthreads();
    float mean = mv[0], r = mv[1];
    float4 ov;
    ov.x = fmaf((xv.x - mean) * r, g[tid*4+0], bb[tid*4+0]);
    ov.y = fmaf((xv.y - mean) * r, g[tid*4+1], bb[tid*4+1]);
    ov.z = fmaf((xv.z - mean) * r, g[tid*4+2], bb[tid*4+2]);
    ov.w = fmaf((xv.w - mean) * r, g[tid*4+3], bb[tid*4+3]);
    *(float4*)(out + base + tid * 4) = ov;
}

// ---------------- launch ----------------
extern "C" void kernel_launch(void* const* d_in, const int* in_sizes, int n_in,
                              void* d_out, int out_size)
{
    (void)in_sizes; (void)n_in; (void)out_size;
    const float* x     = (const float*)d_in[0];
    const float* W_ez  = (const float*)d_in[1];
    const float* b_ez  = (const float*)d_in[2];
    const float* U_h   = (const float*)d_in[3];
    const float* U_z   = (const float*)d_in[4];
    const float* b_u   = (const float*)d_in[5];
    const float* osh   = (const float*)d_in[6];
    const float* lns_g = (const float*)d_in[7];
    const float* lns_b = (const float*)d_in[8];
    const float* ffg   = (const float*)d_in[9];
    const float* ffb   = (const float*)d_in[10];
    const float* W1    = (const float*)d_in[11];
    const float* fb1   = (const float*)d_in[12];
    const float* W2    = (const float*)d_in[13];
    const float* fb2   = (const float*)d_in[14];
    const float* watt  = (const float*)d_in[15];
    /* d_in[16] = b_att: softmax is shift-invariant -> no effect */
    const float* lno_g = (const float*)d_in[17];
    const float* lno_b = (const float*)d_in[18];
    float* out = (float*)d_out;

    void *p0, *p1, *p2, *ps;
    cudaGetSymbolAddress(&p0, g_buf0);
    cudaGetSymbolAddress(&p1, g_buf1);
    cudaGetSymbolAddress(&p2, g_buf2);
    cudaGetSymbolAddress(&ps, g_scores);
    float* zb = (float*)p0;   // z / h1
    float* sb = (float*)p1;   // states / hln
    float* pb = (float*)p2;   // pre-output
    float* scb = (float*)ps;

    // v[h,d], c[h]
    prep_kernel<<<129, 256>>>(W2, fb2, watt);

    // GEMM-A: z = tanh(x @ W_ez + b_ez)   [8192,1024]x[1024,1024]
    gemm_kernel<<<dim3(8, 64, 1), 256>>>(x, 1024, 0, W_ez, 1024, 0,
                                         zb, 1024, 0, 1024,
                                         b_ez, 0, 0, nullptr, nullptr);

    // sequential scan -> states in g_buf1
    scan_kernel<<<dim3(8, 4), 32>>>(U_h, U_z, b_u, lns_g, lns_b);

    // shaped + per-head LN (in place on g_buf1)
    hln_kernel<<<8192, 256>>>(osh, ffg, ffb);

    // GEMM-B (per head): h1 = gelu(hln @ ff_W1[h] + ff_b1[h]) -> g_buf0
    gemm_kernel<<<dim3(1, 64, 8), 256>>>(sb, 1024, 128, W1, 128, Dq * Dq,
                                         zb, 1024, 128, 128,
                                         fb1, 128, 1, nullptr, nullptr);

    // logits -> softmax over heads -> scale h1 in place, store scores
    att_kernel<<<1024, 256>>>();

    // GEMM-C: pre = (s*h1)[8192,1024] @ W2[1024,1024] + sum_h s_h*b2[h,:]
    gemm_kernel<<<dim3(8, 64, 1), 256>>>(zb, 1024, 0, W2, 1024, 0,
                                         pb, 1024, 0, 1024,
                                         nullptr, 0, 2, scb, fb2);

    // final LN over E
    lnout_kernel<<<8192, 256>>>(out, lno_g, lno_b);
}

// round 3
// speedup vs baseline: 1.3643x; 1.3643x over previous
#include <cuda_runtime.h>
#include <math.h>
#include <stdint.h>

#define Bq 4
#define Sq 2048
#define Eq 1024
#define Hq 8
#define Dq 128
#define BS (Bq*Sq)          /* 8192 tokens */
#define HD (Hq*Dq)          /* 1024 */

// ---------------- scratch (static device globals; no allocation) ----------------
__device__ float g_buf0[BS*HD];   // z -> h1 (scaled by scores)
__device__ float g_buf1[BS*HD];   // scan states -> hln
__device__ float g_buf2[BS*Eq];   // pre-output
__device__ float g_v[HD];
__device__ float g_c[Hq];
__device__ float g_scores[BS*Hq];
__device__ float g_wezT[Eq*HD];   // W_ez^T  [HD, E]  (rows = out col, K contiguous)
__device__ float g_w2T[HD*Eq];    // W2^T    [E, HD]
__device__ float g_w1T[Hq*Dq*Dq]; // per-head W1^T [D, D]

// =================== tf32 mma.sync GEMM ===================
// C[128,128] CTA tile. A [M,K] row-major (K contig). Bt [N,K] row-major (K contig)
// -> mma row.col computes A @ Bt^T.
// epi: 0 = tanh(acc+bias[col]); 1 = gelu_exact(acc+bias[col]);
//      2 = acc + sum_h scores[row,h]*b2[h,col]
#define GEMM_SMEM 67584   /* max(2*16KB A + 2*16KB B, 128*132*4 C staging) */

__device__ __forceinline__ uint32_t f2tf32(float v) {
    uint32_t u;
    asm("cvt.rna.tf32.f32 %0, %1;" : "=r"(u) : "f"(v));
    return u;
}

__global__ void __launch_bounds__(256)
mma_gemm(const float* __restrict__ A, int lda, int sAz,
         const float* __restrict__ Bt, int ldb, int sBz,
         float* __restrict__ C, int ldc, int sCz,
         int K,
         const float* __restrict__ bias, int sBiasz, int epi,
         const float* __restrict__ scores, const float* __restrict__ b2)
{
    extern __shared__ float smem[];
    // double-buffered permuted tiles (each 4096 floats = 16KB)
    uint32_t* bufA0 = (uint32_t*)smem;
    uint32_t* bufA1 = (uint32_t*)smem + 4096;
    uint32_t* bufB0 = (uint32_t*)smem + 8192;
    uint32_t* bufB1 = (uint32_t*)smem + 12288;

    const int tid  = threadIdx.x;
    const int lane = tid & 31, wid = tid >> 5;
    const int wm = wid >> 2, wn = wid & 3;           // warp grid 2x4 -> 64x32 per warp
    const int bx = blockIdx.x, by = blockIdx.y, bz = blockIdx.z;

    A  += (size_t)bz * sAz + (size_t)(by * 128) * lda;
    Bt += (size_t)bz * sBz + (size_t)(bx * 128) * ldb;

    const int rA = tid >> 3;          // 0..31 (+p*32)
    const int cA = (tid & 7) * 4;     // 0..28

    float cr[4][4][4];
    #pragma unroll
    for (int i = 0; i < 4; i++)
        #pragma unroll
        for (int j = 0; j < 4; j++)
            #pragma unroll
            for (int k = 0; k < 4; k++) cr[i][j][k] = 0.0f;

    float4 ar[4], br[4];

    // permutation constants (depend only on cA)
    const int ksld   = cA >> 3;
    const int slotA  = 2 * ((cA & 7) >> 2);          // + (rr>>3) at use
    const int slotB  = (cA & 7) >> 2;

    const int nch = K >> 5;

    // ---- prologue: load + store chunk 0 ----
    #pragma unroll
    for (int p = 0; p < 4; p++) {
        ar[p] = *(const float4*)(A  + (size_t)(rA + p * 32) * lda + cA);
        br[p] = *(const float4*)(Bt + (size_t)(rA + p * 32) * ldb + cA);
    }
    #pragma unroll
    for (int p = 0; p < 4; p++) {
        int r = rA + p * 32;
        int mt = r >> 4, rr = r & 15;
        int baseA = (((mt * 4 + ksld) * 32 + (rr & 7) * 4) << 2) + slotA + (rr >> 3);
        bufA0[baseA + 0]  = f2tf32(ar[p].x);
        bufA0[baseA + 4]  = f2tf32(ar[p].y);
        bufA0[baseA + 8]  = f2tf32(ar[p].z);
        bufA0[baseA + 12] = f2tf32(ar[p].w);
        int nt = r >> 3, nn = r & 7;
        int baseB = (((nt * 4 + ksld) * 32 + nn * 4) << 1) + slotB;
        bufB0[baseB + 0] = f2tf32(br[p].x);
        bufB0[baseB + 2] = f2tf32(br[p].y);
        bufB0[baseB + 4] = f2tf32(br[p].z);
        bufB0[baseB + 6] = f2tf32(br[p].w);
    }
    __syncthreads();

    for (int c = 0; c < nch; c++) {
        if (c + 1 < nch) {
            int kt = (c + 1) << 5;
            #pragma unroll
            for (int p = 0; p < 4; p++) {
                ar[p] = *(const float4*)(A  + (size_t)(rA + p * 32) * lda + kt + cA);
                br[p] = *(const float4*)(Bt + (size_t)(rA + p * 32) * ldb + kt + cA);
            }
        }
        const uint32_t* bA = (c & 1) ? bufA1 : bufA0;
        const uint32_t* bB = (c & 1) ? bufB1 : bufB0;
        #pragma unroll
        for (int ks = 0; ks < 4; ks++) {
            uint4 af[4];
            uint2 bf[4];
            #pragma unroll
            for (int mt = 0; mt < 4; mt++)
                af[mt] = *(const uint4*)(bA + ((((wm * 4 + mt) * 4 + ks) * 32 + lane) << 2));
            #pragma unroll
            for (int nt = 0; nt < 4; nt++)
                bf[nt] = *(const uint2*)(bB + ((((wn * 4 + nt) * 4 + ks) * 32 + lane) << 1));
            #pragma unroll
            for (int mt = 0; mt < 4; mt++)
                #pragma unroll
                for (int nt = 0; nt < 4; nt++)
                    asm volatile(
                        "mma.sync.aligned.m16n8k8.row.col.f32.tf32.tf32.f32 "
                        "{%0,%1,%2,%3}, {%4,%5,%6,%7}, {%8,%9}, {%0,%1,%2,%3};"
                        : "+f"(cr[mt][nt][0]), "+f"(cr[mt][nt][1]),
                          "+f"(cr[mt][nt][2]), "+f"(cr[mt][nt][3])
                        : "r"(af[mt].x), "r"(af[mt].y), "r"(af[mt].z), "r"(af[mt].w),
                          "r"(bf[nt].x), "r"(bf[nt].y));
        }
        if (c + 1 < nch) {
            uint32_t* dA = (c & 1) ? bufA0 : bufA1;
            uint32_t* dB = (c & 1) ? bufB0 : bufB1;
            #pragma unroll
            for (int p = 0; p < 4; p++) {
                int r = rA + p * 32;
                int mt = r >> 4, rr = r & 15;
                int baseA = (((mt * 4 + ksld) * 32 + (rr & 7) * 4) << 2) + slotA + (rr >> 3);
                dA[baseA + 0]  = f2tf32(ar[p].x);
                dA[baseA + 4]  = f2tf32(ar[p].y);
                dA[baseA + 8]  = f2tf32(ar[p].z);
                dA[baseA + 12] = f2tf32(ar[p].w);
                int nt = r >> 3, nn = r & 7;
                int baseB = (((nt * 4 + ksld) * 32 + nn * 4) << 1) + slotB;
                dB[baseB + 0] = f2tf32(br[p].x);
                dB[baseB + 2] = f2tf32(br[p].y);
                dB[baseB + 4] = f2tf32(br[p].z);
                dB[baseB + 6] = f2tf32(br[p].w);
            }
        }
        __syncthreads();
    }

    // ---- epilogue: frags -> padded SMEM (raw), then coalesced copy + epi ----
    float* smC = smem;   // stride 132 floats per row
    #pragma unroll
    for (int mt = 0; mt < 4; mt++) {
        int r0 = wm * 64 + mt * 16 + (lane >> 2);
        #pragma unroll
        for (int nt = 0; nt < 4; nt++) {
            int col = wn * 32 + nt * 8 + 2 * (lane & 3);
            smC[r0 * 132 + col]       = cr[mt][nt][0];
            smC[r0 * 132 + col + 1]   = cr[mt][nt][1];
            smC[(r0 + 8) * 132 + col]     = cr[mt][nt][2];
            smC[(r0 + 8) * 132 + col + 1] = cr[mt][nt][3];
        }
    }
    __syncthreads();

    C += (size_t)bz * sCz + (size_t)(by * 128) * ldc + bx * 128;
    const float* biasp = bias ? (bias + (size_t)bz * sBiasz + bx * 128) : nullptr;
    const int colc = lane * 4;
    #pragma unroll
    for (int it = 0; it < 16; it++) {
        int r = it * 8 + wid;
        float4 v = *(const float4*)&smC[r * 132 + colc];
        if (epi == 0) {
            v.x = tanhf(v.x + biasp[colc + 0]);
            v.y = tanhf(v.y + biasp[colc + 1]);
            v.z = tanhf(v.z + biasp[colc + 2]);
            v.w = tanhf(v.w + biasp[colc + 3]);
        } else if (epi == 1) {
            float a0 = v.x + biasp[colc + 0];
            float a1 = v.y + biasp[colc + 1];
            float a2 = v.z + biasp[colc + 2];
            float a3 = v.w + biasp[colc + 3];
            v.x = 0.5f * a0 * (1.0f + erff(a0 * 0.70710678118654752f));
            v.y = 0.5f * a1 * (1.0f + erff(a1 * 0.70710678118654752f));
            v.z = 0.5f * a2 * (1.0f + erff(a2 * 0.70710678118654752f));
            v.w = 0.5f * a3 * (1.0f + erff(a3 * 0.70710678118654752f));
        } else if (epi == 2) {
            int grow = by * 128 + r;
            int gcol = bx * 128 + colc;
            #pragma unroll
            for (int hh = 0; hh < 8; hh++) {
                float sc = scores[grow * 8 + hh];         // warp-uniform (broadcast)
                const float* bp = b2 + hh * Eq + gcol;
                v.x = fmaf(sc, bp[0], v.x);
                v.y = fmaf(sc, bp[1], v.y);
                v.z = fmaf(sc, bp[2], v.z);
                v.w = fmaf(sc, bp[3], v.w);
            }
        }
        *(float4*)(C + (size_t)r * ldc + colc) = v;
    }
}

// ================= weight transpose (B operands to K-major) =================
__global__ void __launch_bounds__(256)
transpose_kernel(const float* __restrict__ S, float* __restrict__ D, int n, int zstride)
{
    __shared__ float t[32][33];
    S += (size_t)blockIdx.z * zstride;
    D += (size_t)blockIdx.z * zstride;
    int x  = blockIdx.x * 32 + threadIdx.x;
    int y0 = blockIdx.y * 32;
    #pragma unroll
    for (int j = 0; j < 32; j += 8)
        t[threadIdx.y + j][threadIdx.x] = S[(size_t)(y0 + threadIdx.y + j) * n + x];
    __syncthreads();
    int x2 = blockIdx.y * 32 + threadIdx.x;
    int y2 = blockIdx.x * 32;
    #pragma unroll
    for (int j = 0; j < 32; j += 8)
        D[(size_t)(y2 + threadIdx.y + j) * n + x2] = t[threadIdx.x][threadIdx.y + j];
}

// ================= sequential MinimalRNN scan: one warp per (b,h) =================
__global__ void __launch_bounds__(32)
scan_kernel(const float* __restrict__ U_h, const float* __restrict__ U_z,
            const float* __restrict__ b_u,
            const float* __restrict__ lns_g, const float* __restrict__ lns_b)
{
    const int h = blockIdx.x, b = blockIdx.y;
    const int lane = threadIdx.x;
    const int d0 = lane * 4;

    float uh[4], uz[4], bu[4], gw[4], gb[4];
    #pragma unroll
    for (int c = 0; c < 4; c++) {
        int d = d0 + c;
        uh[c] = U_h[h * Dq * Dq + d * (Dq + 1)];
        uz[c] = U_z[h * Dq * Dq + d * (Dq + 1)];
        bu[c] = b_u[h * Dq + d];
        gw[c] = lns_g[d];
        gb[c] = lns_b[d];
    }

    float hp[4] = {0.f, 0.f, 0.f, 0.f};
    const int off = ((b * Sq) * Hq + h) * Dq + d0;
    float4 znext = *(const float4*)(g_buf0 + off);

    for (int t = 0; t < Sq; t++) {
        float zt[4] = {znext.x, znext.y, znext.z, znext.w};
        if (t + 1 < Sq)
            znext = *(const float4*)(g_buf0 + off + (t + 1) * HD);

        float hn[4];
        #pragma unroll
        for (int c = 0; c < 4; c++) {
            float a = fmaf(hp[c], uh[c], fmaf(zt[c], uz[c], bu[c]));
            float u = 1.0f / (1.0f + __expf(-a));
            hn[c] = fmaf(u, hp[c] - zt[c], zt[c]);
        }
        float s = (hn[0] + hn[1]) + (hn[2] + hn[3]);
        float q = fmaf(hn[0], hn[0], fmaf(hn[1], hn[1], fmaf(hn[2], hn[2], hn[3] * hn[3])));
        #pragma unroll
        for (int o = 16; o > 0; o >>= 1) {
            s += __shfl_xor_sync(0xffffffffu, s, o);
            q += __shfl_xor_sync(0xffffffffu, q, o);
        }
        float mean = s * (1.0f / Dq);
        float var  = q * (1.0f / Dq) - mean * mean;
        float r = rsqrtf(var + 1e-5f);
        #pragma unroll
        for (int c = 0; c < 4; c++)
            hp[c] = fmaf((hn[c] - mean) * r, gw[c], gb[c]);

        *(float4*)(g_buf1 + off + t * HD) = make_float4(hp[0], hp[1], hp[2], hp[3]);
    }
}

// ================= shaped + per-head LN (in-place on g_buf1) =================
__global__ void __launch_bounds__(256)
hln_kernel(const float* __restrict__ out_shaper,
           const float* __restrict__ ffg, const float* __restrict__ ffb)
{
    int w    = blockIdx.x * 8 + (threadIdx.x >> 5);
    int lane = threadIdx.x & 31;
    int h    = w & 7;
    int d0   = lane * 4;
    int off  = w * Dq + d0;

    float4 xv = *(const float4*)(g_buf1 + off);
    float xs[4] = {xv.x, xv.y, xv.z, xv.w};
    float sh[4];
    #pragma unroll
    for (int c = 0; c < 4; c++) {
        int d = d0 + c;
        sh[c] = xs[c] * out_shaper[h * Dq * Dq + d * (Dq + 1)];
    }
    float s = (sh[0] + sh[1]) + (sh[2] + sh[3]);
    float q = sh[0]*sh[0] + sh[1]*sh[1] + sh[2]*sh[2] + sh[3]*sh[3];
    #pragma unroll
    for (int o = 16; o > 0; o >>= 1) {
        s += __shfl_xor_sync(0xffffffffu, s, o);
        q += __shfl_xor_sync(0xffffffffu, q, o);
    }
    float mean = s * (1.0f / Dq);
    float var  = q * (1.0f / Dq) - mean * mean;
    float r = rsqrtf(var + 1e-5f);
    float4 ov;
    ov.x = fmaf((sh[0] - mean) * r, ffg[h * Dq + d0 + 0], ffb[h * Dq + d0 + 0]);
    ov.y = fmaf((sh[1] - mean) * r, ffg[h * Dq + d0 + 1], ffb[h * Dq + d0 + 1]);
    ov.z = fmaf((sh[2] - mean) * r, ffg[h * Dq + d0 + 2], ffb[h * Dq + d0 + 2]);
    ov.w = fmaf((sh[3] - mean) * r, ffg[h * Dq + d0 + 3], ffb[h * Dq + d0 + 3]);
    *(float4*)(g_buf1 + off) = ov;
}

// ================= v[h,d] = W2[h,d,:]·w_att, c[h] = b2[h,:]·w_att =================
__global__ void __launch_bounds__(256)
prep_kernel(const float* __restrict__ W2, const float* __restrict__ b2,
            const float* __restrict__ watt)
{
    int w    = blockIdx.x * 8 + (threadIdx.x >> 5);
    int lane = threadIdx.x & 31;
    const float* rowp;
    if (w < HD)            rowp = W2 + (size_t)w * Eq;
    else if (w < HD + Hq)  rowp = b2 + (size_t)(w - HD) * Eq;
    else return;

    float p = 0.0f;
    for (int e = lane * 4; e < Eq; e += 128) {
        float4 a  = *(const float4*)(rowp + e);
        float4 ww = *(const float4*)(watt + e);
        p += a.x * ww.x + a.y * ww.y + a.z * ww.z + a.w * ww.w;
    }
    #pragma unroll
    for (int o = 16; o > 0; o >>= 1) p += __shfl_xor_sync(0xffffffffu, p, o);
    if (lane == 0) {
        if (w < HD) g_v[w] = p;
        else        g_c[w - HD] = p;
    }
}

// ================= per-token head softmax + scale h1 in place =================
__global__ void __launch_bounds__(256)
att_kernel()
{
    int token = blockIdx.x * 8 + (threadIdx.x >> 5);
    int lane  = threadIdx.x & 31;
    int base  = token * HD;

    float4 xv[8];
    float lg[8];
    #pragma unroll
    for (int hh = 0; hh < 8; hh++) {
        xv[hh] = *(const float4*)(g_buf0 + base + hh * Dq + lane * 4);
        float4 vv = *(const float4*)(g_v + hh * Dq + lane * 4);
        float p = xv[hh].x * vv.x + xv[hh].y * vv.y + xv[hh].z * vv.z + xv[hh].w * vv.w;
        #pragma unroll
        for (int o = 16; o > 0; o >>= 1) p += __shfl_xor_sync(0xffffffffu, p, o);
        lg[hh] = p + g_c[hh];
    }
    float m = lg[0];
    #pragma unroll
    for (int hh = 1; hh < 8; hh++) m = fmaxf(m, lg[hh]);
    float ex[8]; float sum = 0.0f;
    #pragma unroll
    for (int hh = 0; hh < 8; hh++) { ex[hh] = __expf(lg[hh] - m); sum += ex[hh]; }
    float inv = 1.0f / sum;
    #pragma unroll
    for (int hh = 0; hh < 8; hh++) {
        float sc = ex[hh] * inv;
        xv[hh].x *= sc; xv[hh].y *= sc; xv[hh].z *= sc; xv[hh].w *= sc;
        *(float4*)(g_buf0 + base + hh * Dq + lane * 4) = xv[hh];
    }
    if (lane < 8) g_scores[token * 8 + lane] = ex[lane] * inv;
}

// ================= final LayerNorm over E -> d_out =================
__global__ void __launch_bounds__(256)
lnout_kernel(float* __restrict__ out, const float* __restrict__ g,
             const float* __restrict__ bb)
{
    int row  = blockIdx.x;
    int tid  = threadIdx.x;
    int base = row * Eq;

    float4 xv = *(const float4*)(g_buf2 + base + tid * 4);
    float s = xv.x + xv.y + xv.z + xv.w;
    float q = xv.x*xv.x + xv.y*xv.y + xv.z*xv.z + xv.w*xv.w;
    #pragma unroll
    for (int o = 16; o > 0; o >>= 1) {
        s += __shfl_xor_sync(0xffffffffu, s, o);
        q += __shfl_xor_sync(0xffffffffu, q, o);
    }
    __shared__ float rs[8], rq[8];
    __shared__ float mv[2];
    int warp = tid >> 5, lane = tid & 31;
    if (lane == 0) { rs[warp] = s; rq[warp] = q; }
    __syncthreads();
    if (tid == 0) {
        float S = 0.f, Q = 0.f;
        #pragma unroll
        for (int i = 0; i < 8; i++) { S += rs[i]; Q += rq[i]; }
        float mean = S * (1.0f / Eq);
        float var  = Q * (1.0f / Eq) - mean * mean;
        mv[0] = mean; mv[1] = rsqrtf(var + 1e-5f);
    }
    __syncthreads();
    float mean = mv[0], r = mv[1];
    float4 ov;
    ov.x = fmaf((xv.x - mean) * r, g[tid*4+0], bb[tid*4+0]);
    ov.y = fmaf((xv.y - mean) * r, g[tid*4+1], bb[tid*4+1]);
    ov.z = fmaf((xv.z - mean) * r, g[tid*4+2], bb[tid*4+2]);
    ov.w = fmaf((xv.w - mean) * r, g[tid*4+3], bb[tid*4+3]);
    *(float4*)(out + base + tid * 4) = ov;
}

// ================= launch =================
extern "C" void kernel_launch(void* const* d_in, const int* in_sizes, int n_in,
                              void* d_out, int out_size)
{
    (void)in_sizes; (void)n_in; (void)out_size;
    const float* x     = (const float*)d_in[0];
    const float* W_ez  = (const float*)d_in[1];
    const float* b_ez  = (const float*)d_in[2];
    const float* U_h   = (const float*)d_in[3];
    const float* U_z   = (const float*)d_in[4];
    const float* b_u   = (const float*)d_in[5];
    const float* osh   = (const float*)d_in[6];
    const float* lns_g = (const float*)d_in[7];
    const float* lns_b = (const float*)d_in[8];
    const float* ffg   = (const float*)d_in[9];
    const float* ffb   = (const float*)d_in[10];
    const float* W1    = (const float*)d_in[11];
    const float* fb1   = (const float*)d_in[12];
    const float* W2    = (const float*)d_in[13];
    const float* fb2   = (const float*)d_in[14];
    const float* watt  = (const float*)d_in[15];
    /* d_in[16] = b_att: softmax shift-invariant */
    const float* lno_g = (const float*)d_in[17];
    const float* lno_b = (const float*)d_in[18];
    float* out = (float*)d_out;

    void *p0, *p1, *p2, *ps, *pwez, *pw2, *pw1;
    cudaGetSymbolAddress(&p0, g_buf0);
    cudaGetSymbolAddress(&p1, g_buf1);
    cudaGetSymbolAddress(&p2, g_buf2);
    cudaGetSymbolAddress(&ps, g_scores);
    cudaGetSymbolAddress(&pwez, g_wezT);
    cudaGetSymbolAddress(&pw2, g_w2T);
    cudaGetSymbolAddress(&pw1, g_w1T);
    float* zb   = (float*)p0;
    float* sb   = (float*)p1;
    float* pb   = (float*)p2;
    float* scb  = (float*)ps;
    float* wezT = (float*)pwez;
    float* w2T  = (float*)pw2;
    float* w1T  = (float*)pw1;

    cudaFuncSetAttribute(mma_gemm, cudaFuncAttributeMaxDynamicSharedMemorySize, GEMM_SMEM);

    // small precomputes
    prep_kernel<<<129, 256>>>(W2, fb2, watt);
    transpose_kernel<<<dim3(32, 32, 1), dim3(32, 8)>>>(W_ez, wezT, 1024, 0);
    transpose_kernel<<<dim3(32, 32, 1), dim3(32, 8)>>>(W2, w2T, 1024, 0);
    transpose_kernel<<<dim3(4, 4, 8),  dim3(32, 8)>>>(W1, w1T, 128, Dq * Dq);

    // GEMM-A: z = tanh(x @ W_ez + b_ez)
    mma_gemm<<<dim3(8, 64, 1), 256, GEMM_SMEM>>>(x, 1024, 0, wezT, 1024, 0,
                                                 zb, 1024, 0, 1024,
                                                 b_ez, 0, 0, nullptr, nullptr);

    // sequential scan -> g_buf1
    scan_kernel<<<dim3(8, 4), 32>>>(U_h, U_z, b_u, lns_g, lns_b);

    // shaped + per-head LN
    hln_kernel<<<8192, 256>>>(osh, ffg, ffb);

    // GEMM-B per head: h1 = gelu(hln @ W1[h] + b1[h]) -> g_buf0
    mma_gemm<<<dim3(1, 64, 8), 256, GEMM_SMEM>>>(sb, 1024, 128, w1T, 128, Dq * Dq,
                                                 zb, 1024, 128, 128,
                                                 fb1, 128, 1, nullptr, nullptr);

    // head softmax + scale h1 in place
    att_kernel<<<1024, 256>>>();

    // GEMM-C: pre = (s*h1) @ W2 + sum_h s_h*b2[h,:]
    mma_gemm<<<dim3(8, 64, 1), 256, GEMM_SMEM>>>(zb, 1024, 0, w2T, 1024, 0,
                                                 pb, 1024, 0, 1024,
                                                 nullptr, 0, 2, scb, fb2);

    // final LN over E
    lnout_kernel<<<8192, 256>>>(out, lno_g, lno_b);
}